// round 2
// baseline (speedup 1.0000x reference)
#include <cuda_runtime.h>

#define BB 2
#define SQL 2048
#define SKL 2048
#define DD 1024
#define HH 16
#define DH 64

// Scratch (module-static device globals; allowed per harness rules)
__device__ float g_qh[BB * HH * SQL * DH];   // [B,H,SQ,DH]
__device__ float g_kh[BB * HH * SKL * DH];   // [B,H,SK,DH]
__device__ float g_vh[BB * HH * SKL * DH];   // [B,H,SK,DH]
__device__ float g_cat[BB * SQL * DD];       // [B,SQ,H*DH]
__device__ int   g_mask_kind;                // 0=u8/bool, 1=int32, 2=float32

// ---------------------------------------------------------------------------
// Mask dtype detection: inspect raw bytes of the mask buffer.
//   float32 1.0f has byte 0x80 -> any byte > 1 => float32
//   int32 0/1: every byte at offset%4 != 0 is zero => int32
//   else bytes are independently 0/1 => uint8/bool
// Deterministic (pure function of input bytes).
// ---------------------------------------------------------------------------
__global__ void detect_mask_kind_kernel(const unsigned char* __restrict__ m)
{
    if (threadIdx.x == 0 && blockIdx.x == 0) {
        bool any_big = false, any_nonzero_off = false;
        for (int i = 0; i < 1024; i++) {
            unsigned char b = m[i];
            if (b > 1) any_big = true;
            if ((i & 3) != 0 && b != 0) any_nonzero_off = true;
        }
        g_mask_kind = any_big ? 2 : (any_nonzero_off ? 0 : 1);
    }
}

// ---------------------------------------------------------------------------
// Projection GEMM: Out[b,h,s,e] = sum_d X[b,s,d] * W[h,d,e]
// grid (M/64, H, 3), block 256. 64x64 tile, BK=32, 4x4 per thread.
// ---------------------------------------------------------------------------
__global__ __launch_bounds__(256)
void proj_kernel(const float* __restrict__ qp, const float* __restrict__ kp,
                 const float* __restrict__ vp,
                 const float* __restrict__ Wq, const float* __restrict__ Wk,
                 const float* __restrict__ Wv)
{
    const float* X; const float* W; float* O;
    const int z = blockIdx.z;
    if (z == 0)      { X = qp; W = Wq; O = g_qh; }
    else if (z == 1) { X = kp; W = Wk; O = g_kh; }
    else             { X = vp; W = Wv; O = g_vh; }
    const int h  = blockIdx.y;
    const int m0 = blockIdx.x * 64;
    W += h * (DD * DH);

    __shared__ float As[64][36];   // [m][k], padded row: bank-safe
    __shared__ float Bs[32][64];   // [k][e]

    const int tid = threadIdx.x;
    const int ty = tid >> 4, tx = tid & 15;

    float acc[4][4] = {};

    for (int k0 = 0; k0 < DD; k0 += 32) {
#pragma unroll
        for (int rep = 0; rep < 2; rep++) {
            int idx = rep * 256 + tid;
            int r = idx >> 3;
            int c = (idx & 7) << 2;
            *reinterpret_cast<float4*>(&As[r][c]) =
                *reinterpret_cast<const float4*>(&X[(size_t)(m0 + r) * DD + k0 + c]);
        }
#pragma unroll
        for (int rep = 0; rep < 2; rep++) {
            int idx = rep * 256 + tid;
            int r = idx >> 4;
            int c = (idx & 15) << 2;
            *reinterpret_cast<float4*>(&Bs[r][c]) =
                *reinterpret_cast<const float4*>(&W[(k0 + r) * DH + c]);
        }
        __syncthreads();
#pragma unroll
        for (int p = 0; p < 32; p++) {
            float a[4];
#pragma unroll
            for (int i = 0; i < 4; i++) a[i] = As[4 * ty + i][p];
            float4 b4 = *reinterpret_cast<const float4*>(&Bs[p][4 * tx]);
            float b[4] = {b4.x, b4.y, b4.z, b4.w};
#pragma unroll
            for (int i = 0; i < 4; i++)
#pragma unroll
                for (int j = 0; j < 4; j++)
                    acc[i][j] += a[i] * b[j];
        }
        __syncthreads();
    }

#pragma unroll
    for (int i = 0; i < 4; i++) {
        int m = m0 + 4 * ty + i;
        int bb = m / SQL;
        int s  = m - bb * SQL;
        float4 val = make_float4(acc[i][0], acc[i][1], acc[i][2], acc[i][3]);
        *reinterpret_cast<float4*>(
            &O[(((size_t)bb * HH + h) * SQL + s) * DH + 4 * tx]) = val;
    }
}

// ---------------------------------------------------------------------------
// XOR-4 shared-memory swizzle for 64x64 fp32 tiles (float4-granular).
// ---------------------------------------------------------------------------
__device__ __forceinline__ int swz(int r, int c) {
    return (r << 6) + (((((c >> 2) ^ (r >> 2)) & 15) << 2) | (c & 3));
}

// ---------------------------------------------------------------------------
// Flash attention (fp32, online softmax).
// grid (SQ/64, H, B), block 256 (16x16 threads, 4x4 per thread).
// ---------------------------------------------------------------------------
__global__ __launch_bounds__(256)
void attn_kernel(const void* __restrict__ mask)
{
    __shared__ float Qs[64 * 64];
    __shared__ float KPs[64 * 64];   // K tile, reused as P tile after S-GEMM
    __shared__ float Vs[64 * 64];

    const int qt = blockIdx.x, h = blockIdx.y, bb = blockIdx.z;
    const float* Q = g_qh + (((size_t)bb * HH + h) * SQL + qt * 64) * DH;
    const float* K = g_kh + ((size_t)bb * HH + h) * SKL * DH;
    const float* V = g_vh + ((size_t)bb * HH + h) * SKL * DH;

    const size_t mbase = ((size_t)bb * SQL + qt * 64) * SKL;
    const unsigned char* M8  = (const unsigned char*)mask + mbase;
    const int*           M32 = (const int*)mask + mbase;
    const float*         Mf  = (const float*)mask + mbase;
    const int mk = g_mask_kind;

    const int tid = threadIdx.x;
    const int ty = tid >> 4, tx = tid & 15;

    // Load Q tile, fold in 1/sqrt(DH) = 0.125
#pragma unroll
    for (int rep = 0; rep < 4; rep++) {
        int idx = rep * 256 + tid;
        int r = idx >> 4;
        int c = (idx & 15) << 2;
        float4 v4 = *reinterpret_cast<const float4*>(&Q[r * DH + c]);
        v4.x *= 0.125f; v4.y *= 0.125f; v4.z *= 0.125f; v4.w *= 0.125f;
        *reinterpret_cast<float4*>(&Qs[swz(r, c)]) = v4;
    }

    float m_i[4] = {-1e30f, -1e30f, -1e30f, -1e30f};
    float l_i[4] = {0.f, 0.f, 0.f, 0.f};
    float acc[4][4] = {};

    for (int kt = 0; kt < SKL / 64; kt++) {
        __syncthreads();   // prior-iter reads of KPs/Vs complete
#pragma unroll
        for (int rep = 0; rep < 4; rep++) {
            int idx = rep * 256 + tid;
            int r = idx >> 4;
            int c = (idx & 15) << 2;
            *reinterpret_cast<float4*>(&KPs[swz(r, c)]) =
                *reinterpret_cast<const float4*>(&K[(size_t)(kt * 64 + r) * DH + c]);
            *reinterpret_cast<float4*>(&Vs[swz(r, c)]) =
                *reinterpret_cast<const float4*>(&V[(size_t)(kt * 64 + r) * DH + c]);
        }
        __syncthreads();

        // S = Qs * Ks^T  (both stored [row][dh])
        float s[4][4] = {};
#pragma unroll
        for (int d = 0; d < 64; d++) {
            float a[4], b[4];
#pragma unroll
            for (int i = 0; i < 4; i++) a[i] = Qs[swz(4 * ty + i, d)];
#pragma unroll
            for (int j = 0; j < 4; j++) b[j] = KPs[swz(4 * tx + j, d)];
#pragma unroll
            for (int i = 0; i < 4; i++)
#pragma unroll
                for (int j = 0; j < 4; j++)
                    s[i][j] += a[i] * b[j];
        }
        __syncthreads();   // all K reads done before P overwrites KPs

        // mask + online softmax
#pragma unroll
        for (int i = 0; i < 4; i++) {
            size_t mi = (size_t)(4 * ty + i) * SKL + kt * 64 + 4 * tx;
            int mv0, mv1, mv2, mv3;
            if (mk == 1) {
                int4 mm = *reinterpret_cast<const int4*>(&M32[mi]);
                mv0 = mm.x; mv1 = mm.y; mv2 = mm.z; mv3 = mm.w;
            } else if (mk == 0) {
                uchar4 mm = *reinterpret_cast<const uchar4*>(&M8[mi]);
                mv0 = mm.x; mv1 = mm.y; mv2 = mm.z; mv3 = mm.w;
            } else {
                float4 mm = *reinterpret_cast<const float4*>(&Mf[mi]);
                mv0 = (mm.x != 0.0f); mv1 = (mm.y != 0.0f);
                mv2 = (mm.z != 0.0f); mv3 = (mm.w != 0.0f);
            }
            if (mv0) s[i][0] = -1e30f;
            if (mv1) s[i][1] = -1e30f;
            if (mv2) s[i][2] = -1e30f;
            if (mv3) s[i][3] = -1e30f;

            float rm = fmaxf(fmaxf(s[i][0], s[i][1]), fmaxf(s[i][2], s[i][3]));
#pragma unroll
            for (int off = 8; off >= 1; off >>= 1)
                rm = fmaxf(rm, __shfl_xor_sync(0xffffffffu, rm, off));

            float mnew = fmaxf(m_i[i], rm);
            float corr = __expf(m_i[i] - mnew);
            float p0 = __expf(s[i][0] - mnew);
            float p1 = __expf(s[i][1] - mnew);
            float p2 = __expf(s[i][2] - mnew);
            float p3 = __expf(s[i][3] - mnew);
            float rs = p0 + p1 + p2 + p3;
#pragma unroll
            for (int off = 8; off >= 1; off >>= 1)
                rs += __shfl_xor_sync(0xffffffffu, rs, off);

            l_i[i] = l_i[i] * corr + rs;
            m_i[i] = mnew;
#pragma unroll
            for (int j = 0; j < 4; j++) acc[i][j] *= corr;

            *reinterpret_cast<float4*>(&KPs[swz(4 * ty + i, 4 * tx)]) =
                make_float4(p0, p1, p2, p3);
        }
        __syncthreads();

        // acc += P @ V
#pragma unroll
        for (int d = 0; d < 64; d++) {
            float a[4];
#pragma unroll
            for (int i = 0; i < 4; i++) a[i] = KPs[swz(4 * ty + i, d)];
            float4 b4 = *reinterpret_cast<const float4*>(&Vs[swz(d, 4 * tx)]);
            float b[4] = {b4.x, b4.y, b4.z, b4.w};
#pragma unroll
            for (int i = 0; i < 4; i++)
#pragma unroll
                for (int j = 0; j < 4; j++)
                    acc[i][j] += a[i] * b[j];
        }
    }

    // epilogue: normalize, write head-concat layout [B, SQ, H*DH]
#pragma unroll
    for (int i = 0; i < 4; i++) {
        float inv = 1.0f / l_i[i];
        int qrow = qt * 64 + 4 * ty + i;
        float4 o = make_float4(acc[i][0] * inv, acc[i][1] * inv,
                               acc[i][2] * inv, acc[i][3] * inv);
        *reinterpret_cast<float4*>(
            &g_cat[((size_t)bb * SQL + qrow) * DD + h * DH + 4 * tx]) = o;
    }
}

// ---------------------------------------------------------------------------
// Output GEMM: out[m, n] = sum_d cat[m, d] * Wo[d, n];  M=4096, N=K=1024
// ---------------------------------------------------------------------------
__global__ __launch_bounds__(256)
void outproj_kernel(const float* __restrict__ Wo, float* __restrict__ out)
{
    const int m0 = blockIdx.x * 64;
    const int n0 = blockIdx.y * 64;

    __shared__ float As[64][36];
    __shared__ float Bs[32][64];

    const int tid = threadIdx.x;
    const int ty = tid >> 4, tx = tid & 15;

    float acc[4][4] = {};

    for (int k0 = 0; k0 < DD; k0 += 32) {
#pragma unroll
        for (int rep = 0; rep < 2; rep++) {
            int idx = rep * 256 + tid;
            int r = idx >> 3;
            int c = (idx & 7) << 2;
            *reinterpret_cast<float4*>(&As[r][c]) =
                *reinterpret_cast<const float4*>(&g_cat[(size_t)(m0 + r) * DD + k0 + c]);
        }
#pragma unroll
        for (int rep = 0; rep < 2; rep++) {
            int idx = rep * 256 + tid;
            int r = idx >> 4;
            int c = (idx & 15) << 2;
            *reinterpret_cast<float4*>(&Bs[r][c]) =
                *reinterpret_cast<const float4*>(&Wo[(size_t)(k0 + r) * DD + n0 + c]);
        }
        __syncthreads();
#pragma unroll
        for (int p = 0; p < 32; p++) {
            float a[4];
#pragma unroll
            for (int i = 0; i < 4; i++) a[i] = As[4 * ty + i][p];
            float4 b4 = *reinterpret_cast<const float4*>(&Bs[p][4 * tx]);
            float b[4] = {b4.x, b4.y, b4.z, b4.w};
#pragma unroll
            for (int i = 0; i < 4; i++)
#pragma unroll
                for (int j = 0; j < 4; j++)
                    acc[i][j] += a[i] * b[j];
        }
        __syncthreads();
    }

#pragma unroll
    for (int i = 0; i < 4; i++) {
        float4 val = make_float4(acc[i][0], acc[i][1], acc[i][2], acc[i][3]);
        *reinterpret_cast<float4*>(
            &out[(size_t)(m0 + 4 * ty + i) * DD + n0 + 4 * tx]) = val;
    }
}

// ---------------------------------------------------------------------------
extern "C" void kernel_launch(void* const* d_in, const int* in_sizes, int n_in,
                              void* d_out, int out_size)
{
    const float* q  = (const float*)d_in[0];
    const float* k  = (const float*)d_in[1];
    const float* v  = (const float*)d_in[2];
    const void*  mask = d_in[3];
    const float* Wq = (const float*)d_in[4];
    const float* Wk = (const float*)d_in[5];
    const float* Wv = (const float*)d_in[6];
    const float* Wo = (const float*)d_in[7];
    float* out = (float*)d_out;

    detect_mask_kind_kernel<<<1, 32>>>((const unsigned char*)mask);

    dim3 pg((BB * SQL) / 64, HH, 3);
    proj_kernel<<<pg, 256>>>(q, k, v, Wq, Wk, Wv);

    dim3 ag(SQL / 64, HH, BB);
    attn_kernel<<<ag, 256>>>(mask);

    dim3 og((BB * SQL) / 64, DD / 64);
    outproj_kernel<<<og, 256>>>(Wo, out);
}